// round 8
// baseline (speedup 1.0000x reference)
#include <cuda_runtime.h>
#include <cstdint>

// MaxUnpooling2D: updates [16,64,64,256] f32, mask [16,64,64,256] i32
// (flattened per-batch output index), out [16,128,128,256] f32.
//
// Each pooled element scatters into its OWN 2x2 window at the SAME channel
// => output cells are covered exactly once. Fused zero-fill + scatter.
//
// R8: 256-bit (v8) global loads/stores — sm_100a-only. Each thread owns 8
// consecutive channels; every warp access is 1024B dense (vs 512B with
// float4). Halves instruction/wavefront count per byte, doubles per-
// transaction burst contiguity. Unlike R5, density is preserved.

#define C_  256
#define WO_ 128
#define HOWOC_ (128 * 128 * 256)   // per-batch output elements

__device__ __forceinline__ void ldg_v8(const void* p, uint32_t r[8]) {
    asm volatile("ld.global.v8.b32 {%0,%1,%2,%3,%4,%5,%6,%7}, [%8];"
        : "=r"(r[0]), "=r"(r[1]), "=r"(r[2]), "=r"(r[3]),
          "=r"(r[4]), "=r"(r[5]), "=r"(r[6]), "=r"(r[7])
        : "l"(p));
}

__device__ __forceinline__ void stg_v8(void* p, const uint32_t r[8]) {
    asm volatile("st.global.v8.b32 [%0], {%1,%2,%3,%4,%5,%6,%7,%8};"
        :: "l"(p),
           "r"(r[0]), "r"(r[1]), "r"(r[2]), "r"(r[3]),
           "r"(r[4]), "r"(r[5]), "r"(r[6]), "r"(r[7])
        : "memory");
}

__global__ void __launch_bounds__(256) max_unpool_kernel(
    const uint32_t* __restrict__ upd,
    const int*      __restrict__ msk,
    float*          __restrict__ out,
    int n8)
{
    int t = blockIdx.x * blockDim.x + threadIdx.x;
    if (t >= n8) return;

    // One 32B load each for mask and updates (warp: 1024B dense bursts).
    uint32_t mu[8], uu[8];
    ldg_v8(msk + 8 * t, mu);
    ldg_v8(upd + 8 * t, uu);

    // Decode: bit layout of t: c8 [0,5), w [5,11), h [11,17), b [17,21).
    int c8 = t & 31;
    int w  = (t >> 5)  & 63;
    int h  = (t >> 11) & 63;
    int b  = t >> 17;

    // Per-batch flattened address of window cell (0,0), channel 8*c8.
    int base = h * (2 * WO_ * C_) + w * (2 * C_) + (c8 << 3);

    float* ob = out + (size_t)b * HOWOC_ + base;

    // Window-cell offsets: (di*Wo + dj)*C for (di,dj) in {0,1}^2.
    const int offs[4] = {0, C_, WO_ * C_, WO_ * C_ + C_};

#pragma unroll
    for (int k = 0; k < 4; k++) {
        int a = base + offs[k];
        uint32_t v[8];
#pragma unroll
        for (int j = 0; j < 8; j++)
            v[j] = ((int)mu[j] == a + j) ? uu[j] : 0u;
        stg_v8(ob + offs[k], v);
    }
}

extern "C" void kernel_launch(void* const* d_in, const int* in_sizes, int n_in,
                              void* d_out, int out_size)
{
    const uint32_t* upd = (const uint32_t*)d_in[0];
    const int*      msk = (const int*)d_in[1];
    float*          out = (float*)d_out;

    int n  = in_sizes[0];       // 16*64*64*256 = 16,777,216
    int n8 = n >> 3;            // 2,097,152 work items (8 channels each)

    int threads = 256;
    int blocks  = (n8 + threads - 1) / threads;   // 8192
    max_unpool_kernel<<<blocks, threads>>>(upd, msk, out, n8);
}